// round 15
// baseline (speedup 1.0000x reference)
#include <cuda_runtime.h>
#include <cuda_fp16.h>
#include <math.h>
#include <stdint.h>

#define Bsz 16
#define Nn 1024
#define Dd 512
#define Kk 8
#define NITERS 3
#define EPSV 1e-8f
#define LNEPS 1e-5f
#define LOG2PI 1.8378770664093453f
#define SPLITS 32
#define RPB (Nn / SPLITS)   // 32 rows per split block
#define GCH 32              // gll rows per chunk
#define NCH (Nn / GCH)      // 32 chunks

// ------------------- scratch (device globals, no runtime alloc) -------------
__device__ __half g_keysh[Bsz * Nn * Dd];    // 16 MB (fp16 keys)
__device__ __half g_valuesh[Bsz * Nn * Dd];  // 16 MB (fp16 values)
__device__ __half g_WTh[1024 * Dd];          // [Wk^T | Wv^T] as half
__device__ float g_WTq[Dd * Dd];             // Wq^T as float
__device__ float g_mean[Bsz * Nn];
__device__ float g_rstd[Bsz * Nn];
__device__ float g_q[Bsz * Kk * Dd];
__device__ float g_sigma[Bsz * Kk * Dd];
__device__ float g_iv[Bsz * Kk * Dd];
__device__ float g_cpart[Bsz * Kk * 2];      // split log-det constant
__device__ float g_mix[Bsz * Kk];
__device__ float g_attn[Bsz * Nn * Kk];      // row-normalized only
__device__ float g_colpart[Bsz * NCH * Kk];  // per-chunk partial colsums
__device__ float g_colsum[Bsz * Kk];
__device__ float g_snorm[Bsz * Kk];
__device__ float g_mu[Bsz * Kk * Dd];
__device__ __half g_parth[Bsz * SPLITS * Kk * Dd];   // 4 MB (fp16 partials)
__device__ __half g_part2h[Bsz * SPLITS * Kk * Dd];  // 4 MB

// ============ fused prologue: LN stats + weight transposes ==================
__global__ __launch_bounds__(256)
void fused_pre_kernel(const float* __restrict__ emb,
                      const float* __restrict__ Wk,
                      const float* __restrict__ Wv,
                      const float* __restrict__ Wq) {
    int t = threadIdx.x;
    if (blockIdx.x < Bsz * Nn) {
        int row = blockIdx.x;
        const float2* p = (const float2*)(emb + (size_t)row * Dd);
        float2 v = p[t];                      // 256 * 2 = 512
        float s  = v.x + v.y;
        float ss = v.x * v.x + v.y * v.y;
#pragma unroll
        for (int o = 16; o > 0; o >>= 1) {
            s  += __shfl_down_sync(0xFFFFFFFFu, s, o);
            ss += __shfl_down_sync(0xFFFFFFFFu, ss, o);
        }
        __shared__ float sh[16];
        int w = t >> 5, l = t & 31;
        if (l == 0) { sh[w] = s; sh[8 + w] = ss; }
        __syncthreads();
        if (t == 0) {
            s = 0.f; ss = 0.f;
            for (int i = 0; i < 8; i++) { s += sh[i]; ss += sh[8 + i]; }
            float m   = s / (float)Dd;
            float var = ss / (float)Dd - m * m;
            g_mean[row] = m;
            g_rstd[row] = rsqrtf(var + LNEPS);
        }
    } else {
        __shared__ float tt[32][33];
        int r = blockIdx.x - Bsz * Nn;        // 0..767
        int z = r >> 8;                       // 0..2
        int ry = (r >> 4) & 15, rx = r & 15;
        const float* W = (z == 0) ? Wk : (z == 1) ? Wv : Wq;
        int bx = rx * 32, by = ry * 32;
        int tx = t & 31, ty = t >> 5;         // 32 x 8
#pragma unroll
        for (int i = 0; i < 32; i += 8)
            tt[ty + i][tx] = W[(size_t)(by + ty + i) * Dd + bx + tx];
        __syncthreads();
        if (z < 2) {
            int nb = z * 512 + bx;
#pragma unroll
            for (int i = 0; i < 32; i += 8)
                g_WTh[(size_t)(nb + ty + i) * Dd + by + tx] = __float2half(tt[tx][ty + i]);
        } else {
#pragma unroll
            for (int i = 0; i < 32; i += 8)
                g_WTq[(size_t)(bx + ty + i) * Dd + by + tx] = tt[tx][ty + i];
        }
    }
}

// ------------------- fused LN + fp16 GEMM (ldmatrix) + merged qinit ---------
#define GBM 128
#define GBN 128
#define GBK 32
#define LDH 40                       // 32 data halves + 8 pad (bank bijection)
#define TILEH (GBM * LDH)            // 5120 halves per buffer

__device__ __forceinline__ void mma_f16(float* c, const unsigned* a, const unsigned* b) {
    asm volatile(
        "mma.sync.aligned.m16n8k16.row.col.f32.f16.f16.f32 "
        "{%0,%1,%2,%3}, {%4,%5,%6,%7}, {%8,%9}, {%0,%1,%2,%3};"
        : "+f"(c[0]), "+f"(c[1]), "+f"(c[2]), "+f"(c[3])
        : "r"(a[0]), "r"(a[1]), "r"(a[2]), "r"(a[3]), "r"(b[0]), "r"(b[1]));
}
__device__ __forceinline__ void ldsm_x4(unsigned* r, uint32_t addr) {
    asm volatile("ldmatrix.sync.aligned.m8n8.x4.shared.b16 {%0,%1,%2,%3}, [%4];"
                 : "=r"(r[0]), "=r"(r[1]), "=r"(r[2]), "=r"(r[3]) : "r"(addr));
}

#define GEMM_SMEM (4 * TILEH * 2)    // 40960 bytes dynamic

// qinit body: executed by z=1 blocks (qb = 0..127 -> b = qb>>3, by = qb&7)
__device__ void qinit_body(char* smraw, int b, int by,
                           const float* __restrict__ mu_s,
                           const float* __restrict__ logsig,
                           const float* __restrict__ noise,
                           const float* __restrict__ bq,
                           const float* __restrict__ mixc) {
    float* s_sh  = (float*)smraw;          // Kk*Dd = 16 KB
    float* lg_sh = s_sh + Kk * Dd;         // 16 KB
    int t = threadIdx.x;                   // 256
    for (int i = t; i < Kk * Dd; i += 256) {
        float sg = expf(logsig[i]);
        float sl = mu_s[i] + sg * noise[b * Kk * Dd + i];
        s_sh[i] = sl;
        if (by == 0) {
            g_sigma[b * Kk * Dd + i] = sg;
            g_iv[b * Kk * Dd + i] = 1.f / (sg * sg + EPSV);
            lg_sh[i] = logf(fabsf(sg) + EPSV);
        }
    }
    if (by == 0 && t < Kk) g_mix[b * Kk + t] = mixc[t];
    __syncthreads();
    int w = t >> 5, lane = t & 31;
    if (by == 0) {
        float ls = 0.f;
#pragma unroll
        for (int j = 0; j < 16; j++) ls += lg_sh[w * Dd + lane + j * 32];
#pragma unroll
        for (int o = 16; o > 0; o >>= 1) ls += __shfl_down_sync(0xFFFFFFFFu, ls, o);
        if (lane == 0) {
            g_cpart[(b * Kk + w) * 2]     = -0.5f * (float)Dd * LOG2PI - 0.5f * ls;
            g_cpart[(b * Kk + w) * 2 + 1] = 0.f;
        }
    }
#pragma unroll
    for (int jj = 0; jj < 8; jj++) {
        int j = by * 64 + w * 8 + jj;
        float acc[Kk];
#pragma unroll
        for (int k = 0; k < Kk; k++) acc[k] = 0.f;
#pragma unroll
        for (int i = 0; i < 4; i++) {
            float4 wq = *(const float4*)&g_WTq[(size_t)j * Dd + i * 128 + lane * 4];
#pragma unroll
            for (int k = 0; k < Kk; k++) {
                float4 s4 = *(const float4*)&s_sh[k * Dd + i * 128 + lane * 4];
                acc[k] += s4.x * wq.x + s4.y * wq.y + s4.z * wq.z + s4.w * wq.w;
            }
        }
#pragma unroll
        for (int o = 16; o > 0; o >>= 1)
#pragma unroll
            for (int k = 0; k < Kk; k++)
                acc[k] += __shfl_xor_sync(0xFFFFFFFFu, acc[k], o);
        if (lane < Kk) g_q[(b * Kk + lane) * Dd + j] = acc[lane] + bq[j];
    }
}

__global__ __launch_bounds__(256, 2)
void gemm_qinit_f16(const float* __restrict__ emb,
                    const float* __restrict__ bk, const float* __restrict__ bv,
                    const float* __restrict__ ln_g, const float* __restrict__ ln_b,
                    const float* __restrict__ mu_s,
                    const float* __restrict__ logsig,
                    const float* __restrict__ noise,
                    const float* __restrict__ bq,
                    const float* __restrict__ mixc) {
    extern __shared__ char smraw[];
    if (blockIdx.z == 1) {
        if (blockIdx.x != 0) return;       // only 128 of the z=1 blocks work
        qinit_body(smraw, (int)(blockIdx.y >> 3), (int)(blockIdx.y & 7),
                   mu_s, logsig, noise, bq, mixc);
        return;
    }
    __half* hs = (__half*)smraw;
    __half* Abuf[2] = { hs, hs + TILEH };
    __half* Bbuf[2] = { hs + 2 * TILEH, hs + 3 * TILEH };
    __shared__ float s_mean[GBM], s_rstd[GBM];
    __shared__ float s_lng[Dd], s_lnb[Dd];

    int tid = threadIdx.x;
    int bm = blockIdx.y * GBM;
    int bn = blockIdx.x * GBN;

    if (tid < GBM) { s_mean[tid] = g_mean[bm + tid]; s_rstd[tid] = g_rstd[bm + tid]; }
    for (int i = tid; i < Dd; i += 256) { s_lng[i] = ln_g[i]; s_lnb[i] = ln_b[i]; }
    __syncthreads();

    int lane = tid & 31, wrp = tid >> 5;
    int warpM = (wrp & 1) * 64, warpN = (wrp >> 1) * 32;
    int g = lane >> 2, ti = lane & 3;

    uint32_t sA[2] = { (uint32_t)__cvta_generic_to_shared(Abuf[0]),
                       (uint32_t)__cvta_generic_to_shared(Abuf[1]) };
    uint32_t sB[2] = { (uint32_t)__cvta_generic_to_shared(Bbuf[0]),
                       (uint32_t)__cvta_generic_to_shared(Bbuf[1]) };
    uint32_t aoff[4], boff[2];
#pragma unroll
    for (int mf = 0; mf < 4; mf++)
        aoff[mf] = ((warpM + mf * 16 + (lane & 15)) * LDH + ((lane >> 4) * 8)) * 2;
#pragma unroll
    for (int j = 0; j < 2; j++)
        boff[j] = ((warpN + j * 16 + (lane & 7) + ((lane >> 4) & 1) * 8) * LDH
                   + (((lane >> 3) & 1) * 8)) * 2;

    float acc[4][4][4];
#pragma unroll
    for (int mf = 0; mf < 4; mf++)
#pragma unroll
        for (int nf = 0; nf < 4; nf++)
#pragma unroll
            for (int c = 0; c < 4; c++) acc[mf][nf][c] = 0.f;

    float4 pa[4];
    uint4  pw[2];

#pragma unroll
    for (int i = 0; i < 4; i++) {
        int idx = tid + i * 256;
        int m = idx >> 3, c4 = (idx & 7) * 4;
        pa[i] = *(const float4*)&emb[(size_t)(bm + m) * Dd + c4];
    }
#pragma unroll
    for (int i = 0; i < 2; i++) {
        int idx = tid + i * 256;
        int n = idx >> 2, hc = (idx & 3) * 8;
        pw[i] = *(const uint4*)&g_WTh[(size_t)(bn + n) * Dd + hc];
    }
    {
#pragma unroll
        for (int i = 0; i < 4; i++) {
            int idx = tid + i * 256;
            int m = idx >> 3, c4 = (idx & 7) * 4;
            float mu = s_mean[m], rs = s_rstd[m];
            float ax = (pa[i].x - mu) * rs * s_lng[c4]     + s_lnb[c4];
            float ay = (pa[i].y - mu) * rs * s_lng[c4 + 1] + s_lnb[c4 + 1];
            float az = (pa[i].z - mu) * rs * s_lng[c4 + 2] + s_lnb[c4 + 2];
            float aw = (pa[i].w - mu) * rs * s_lng[c4 + 3] + s_lnb[c4 + 3];
            *(half2*)&Abuf[0][m * LDH + c4]     = __float22half2_rn(make_float2(ax, ay));
            *(half2*)&Abuf[0][m * LDH + c4 + 2] = __float22half2_rn(make_float2(az, aw));
        }
#pragma unroll
        for (int i = 0; i < 2; i++) {
            int idx = tid + i * 256;
            int n = idx >> 2, hc = (idx & 3) * 8;
            *(uint4*)&Bbuf[0][n * LDH + hc] = pw[i];
        }
    }
    __syncthreads();

    const int NSTEP = Dd / GBK;        // 16
    int p = 0;
    for (int step = 0; step < NSTEP; step++) {
        int k0n = (step + 1) * GBK;
        if (step + 1 < NSTEP) {
#pragma unroll
            for (int i = 0; i < 4; i++) {
                int idx = tid + i * 256;
                int m = idx >> 3, c4 = (idx & 7) * 4;
                pa[i] = *(const float4*)&emb[(size_t)(bm + m) * Dd + k0n + c4];
            }
#pragma unroll
            for (int i = 0; i < 2; i++) {
                int idx = tid + i * 256;
                int n = idx >> 2, hc = (idx & 3) * 8;
                pw[i] = *(const uint4*)&g_WTh[(size_t)(bn + n) * Dd + k0n + hc];
            }
        }
#pragma unroll
        for (int ks = 0; ks < 2; ks++) {
            uint32_t kboff = ks * 32;  // 16 halves = 32 bytes
            unsigned afr[4][4], bfr[4][2];
#pragma unroll
            for (int mf = 0; mf < 4; mf++)
                ldsm_x4(afr[mf], sA[p] + aoff[mf] + kboff);
            {
                unsigned bq0[4], bq1[4];
                ldsm_x4(bq0, sB[p] + boff[0] + kboff);
                ldsm_x4(bq1, sB[p] + boff[1] + kboff);
                bfr[0][0] = bq0[0]; bfr[0][1] = bq0[1];
                bfr[1][0] = bq0[2]; bfr[1][1] = bq0[3];
                bfr[2][0] = bq1[0]; bfr[2][1] = bq1[1];
                bfr[3][0] = bq1[2]; bfr[3][1] = bq1[3];
            }
#pragma unroll
            for (int mf = 0; mf < 4; mf++)
#pragma unroll
                for (int nf = 0; nf < 4; nf++)
                    mma_f16(acc[mf][nf], afr[mf], bfr[nf]);
        }
        if (step + 1 < NSTEP) {
            int np = p ^ 1;
            __syncthreads();
#pragma unroll
            for (int i = 0; i < 4; i++) {
                int idx = tid + i * 256;
                int m = idx >> 3, c4 = (idx & 7) * 4;
                float mu = s_mean[m], rs = s_rstd[m];
                float ax = (pa[i].x - mu) * rs * s_lng[k0n + c4]     + s_lnb[k0n + c4];
                float ay = (pa[i].y - mu) * rs * s_lng[k0n + c4 + 1] + s_lnb[k0n + c4 + 1];
                float az = (pa[i].z - mu) * rs * s_lng[k0n + c4 + 2] + s_lnb[k0n + c4 + 2];
                float aw = (pa[i].w - mu) * rs * s_lng[k0n + c4 + 3] + s_lnb[k0n + c4 + 3];
                *(half2*)&Abuf[np][m * LDH + c4]     = __float22half2_rn(make_float2(ax, ay));
                *(half2*)&Abuf[np][m * LDH + c4 + 2] = __float22half2_rn(make_float2(az, aw));
            }
#pragma unroll
            for (int i = 0; i < 2; i++) {
                int idx = tid + i * 256;
                int n = idx >> 2, hc = (idx & 3) * 8;
                *(uint4*)&Bbuf[np][n * LDH + hc] = pw[i];
            }
            __syncthreads();
            p = np;
        }
    }

    // epilogue: keys & values both fp16
    int coloff = bn & (Dd - 1);
    __half* Cout = (bn < Dd) ? g_keysh : g_valuesh;
    const float* bias = (bn < Dd) ? bk : bv;
#pragma unroll
    for (int mf = 0; mf < 4; mf++) {
        int row = bm + warpM + mf * 16 + g;
#pragma unroll
        for (int nf = 0; nf < 4; nf++) {
            int col = coloff + warpN + nf * 8 + 2 * ti;
            float b0 = bias[col], b1 = bias[col + 1];
            *(__half2*)&Cout[(size_t)row * Dd + col] =
                __floats2half2_rn(acc[mf][nf][0] + b0, acc[mf][nf][1] + b1);
            *(__half2*)&Cout[(size_t)(row + 8) * Dd + col] =
                __floats2half2_rn(acc[mf][nf][2] + b0, acc[mf][nf][3] + b1);
        }
    }
}

// ---- gll: warp = one slot k, fp16 keys, 32-row chunks ----------------------
__global__ __launch_bounds__(256)
void gll_kernel() {
    int b = blockIdx.y;
    int chunk = blockIdx.x;            // 32 chunks of 32 rows
    int t = threadIdx.x;               // 256 = 8 warps = 8 slots
    int k = t >> 5, lane = t & 31;
    __shared__ float gll_sh[Kk][36];   // padded

    float4 qr[4], ivr[4];
    size_t tb = (size_t)(b * Kk + k) * Dd;
    int d0 = lane * 8;
#pragma unroll
    for (int h = 0; h < 2; h++)
#pragma unroll
        for (int j = 0; j < 2; j++) {
            qr[h * 2 + j]  = *(const float4*)&g_q[tb + h * 256 + d0 + j * 4];
            ivr[h * 2 + j] = *(const float4*)&g_iv[tb + h * 256 + d0 + j * 4];
        }
    float cc = g_cpart[(b * Kk + k) * 2] + g_cpart[(b * Kk + k) * 2 + 1];
    float mx = g_mix[b * Kk + k];
    int nbase = chunk * GCH;
    const __half* kb = g_keysh + ((size_t)(b * Nn + nbase)) * Dd;

#pragma unroll 4
    for (int r = 0; r < GCH; r++) {
        const uint4* kr = (const uint4*)(kb + (size_t)r * Dd);
        uint4 p0 = kr[lane];
        uint4 p1 = kr[32 + lane];
        float s = 0.f;
        const __half2* h0 = (const __half2*)&p0;
        const __half2* h1 = (const __half2*)&p1;
#pragma unroll
        for (int j = 0; j < 2; j++) {
            float2 a0 = __half22float2(h0[j * 2]);
            float2 a1 = __half22float2(h0[j * 2 + 1]);
            float dx = a0.x - qr[j].x, dy = a0.y - qr[j].y;
            float dz = a1.x - qr[j].z, dw = a1.y - qr[j].w;
            s += dx * dx * ivr[j].x + dy * dy * ivr[j].y
               + dz * dz * ivr[j].z + dw * dw * ivr[j].w;
            float2 b0 = __half22float2(h1[j * 2]);
            float2 b1 = __half22float2(h1[j * 2 + 1]);
            float ex = b0.x - qr[2 + j].x, ey = b0.y - qr[2 + j].y;
            float ez = b1.x - qr[2 + j].z, ew = b1.y - qr[2 + j].w;
            s += ex * ex * ivr[2 + j].x + ey * ey * ivr[2 + j].y
               + ez * ez * ivr[2 + j].z + ew * ew * ivr[2 + j].w;
        }
#pragma unroll
        for (int o = 16; o > 0; o >>= 1) s += __shfl_xor_sync(0xFFFFFFFFu, s, o);
        if (lane == 0) gll_sh[k][r] = mx * (cc - 0.5f * s);
    }
    __syncthreads();

    if (t < GCH) {
        float v[Kk], rs = 0.f;
#pragma unroll
        for (int kk = 0; kk < Kk; kk++) { v[kk] = gll_sh[kk][t]; rs += v[kk]; }
        float inv = 1.f / rs;
        float a[Kk];
#pragma unroll
        for (int kk = 0; kk < Kk; kk++) a[kk] = v[kk] * inv;
        float* ap = g_attn + ((size_t)(b * Nn + nbase + t)) * Kk;
        float4 o0 = { a[0], a[1], a[2], a[3] };
        float4 o1 = { a[4], a[5], a[6], a[7] };
        *(float4*)ap = o0;
        *(float4*)(ap + 4) = o1;
#pragma unroll
        for (int o = 16; o > 0; o >>= 1)
#pragma unroll
            for (int kk = 0; kk < Kk; kk++)
                a[kk] += __shfl_xor_sync(0xFFFFFFFFu, a[kk], o);
        if (t == 0)
#pragma unroll
            for (int kk = 0; kk < Kk; kk++)
                g_colpart[(b * NCH + chunk) * Kk + kk] = a[kk];
    }
}

// ------ fused mu & sigma partials + in-block colsum (fp16 partial stores) ---
__global__ __launch_bounds__(256)
void musig_part_kernel() {
    int b = blockIdx.y, s = blockIdx.x;    // s: 0..31
    __shared__ float a_sh[RPB][Kk];        // 1 KB
    __shared__ float cs_sh[Kk];
    int t = threadIdx.x;                   // 256; owns cols 2t, 2t+1
    if (t < Kk) {
        float tot = 0.f;
#pragma unroll
        for (int c = 0; c < NCH; c++) tot += g_colpart[(b * NCH + c) * Kk + t];
        cs_sh[t] = tot + EPSV;
        if (s == 0) {
            g_colsum[b * Kk + t] = tot;
            float sf = tot / (tot + EPSV);
            g_snorm[b * Kk + t] = sf;
            g_mix[b * Kk + t] = sf / (float)Nn;   // for next iteration's gll
        }
    }
    __syncthreads();
    if (t < RPB * Kk)
        a_sh[t >> 3][t & 7] = g_attn[((size_t)(b * Nn + s * RPB)) * Kk + t]
                              / cs_sh[t & 7];
    __syncthreads();
    float acc1x[Kk], acc1y[Kk], acc2x[Kk], acc2y[Kk];
#pragma unroll
    for (int k = 0; k < Kk; k++) {
        acc1x[k] = 0.f; acc1y[k] = 0.f; acc2x[k] = 0.f; acc2y[k] = 0.f;
    }
    const __half2* vb = (const __half2*)(g_valuesh
                        + ((size_t)(b * Nn + s * RPB)) * Dd) + t;
    for (int r = 0; r < RPB; r += 4) {
        float2 v0 = __half22float2(vb[(size_t)(r + 0) * (Dd / 2)]);
        float2 v1 = __half22float2(vb[(size_t)(r + 1) * (Dd / 2)]);
        float2 v2 = __half22float2(vb[(size_t)(r + 2) * (Dd / 2)]);
        float2 v3 = __half22float2(vb[(size_t)(r + 3) * (Dd / 2)]);
#pragma unroll
        for (int k = 0; k < Kk; k++) {
            float a0 = a_sh[r][k], a1 = a_sh[r + 1][k];
            float a2 = a_sh[r + 2][k], a3 = a_sh[r + 3][k];
            acc1x[k] += a0 * v0.x + a1 * v1.x + a2 * v2.x + a3 * v3.x;
            acc1y[k] += a0 * v0.y + a1 * v1.y + a2 * v2.y + a3 * v3.y;
            acc2x[k] += a0 * v0.x * v0.x + a1 * v1.x * v1.x
                      + a2 * v2.x * v2.x + a3 * v3.x * v3.x;
            acc2y[k] += a0 * v0.y * v0.y + a1 * v1.y * v1.y
                      + a2 * v2.y * v2.y + a3 * v3.y * v3.y;
        }
    }
#pragma unroll
    for (int k = 0; k < Kk; k++) {
        size_t idx = (((size_t)b * SPLITS + s) * Kk + k) * (Dd / 2) + t;
        ((__half2*)g_parth)[idx]  = __floats2half2_rn(acc1x[k], acc1y[k]);
        ((__half2*)g_part2h)[idx] = __floats2half2_rn(acc2x[k], acc2y[k]);
    }
}

// reduce (column-split): mu, sigma, iv + partial log-det ---------------------
__global__ __launch_bounds__(128)
void musig_reduce_kernel() {
    int yh = blockIdx.x;               // 0..1 column half
    int bk = blockIdx.y;               // 0..127
    int b = bk >> 3, k = bk & 7;
    int t = threadIdx.x;               // 128; owns cols yh*256 + 2t, +1
    float mx = 0.f, my = 0.f, q2x = 0.f, q2y = 0.f;
#pragma unroll 8
    for (int s = 0; s < SPLITS; s++) {
        size_t idx = (((size_t)b * SPLITS + s) * Kk + k) * (Dd / 2) + yh * 128 + t;
        float2 p1 = __half22float2(((const __half2*)g_parth)[idx]);
        float2 p2 = __half22float2(((const __half2*)g_part2h)[idx]);
        mx += p1.x; my += p1.y;
        q2x += p2.x; q2y += p2.y;
    }
    float sfac = g_snorm[bk];
    float sigx = q2x - (2.f - sfac) * mx * mx;
    float sigy = q2y - (2.f - sfac) * my * my;
    int i0 = bk * Dd + yh * 256 + 2 * t;
    *(float2*)&g_mu[i0]    = make_float2(mx, my);
    *(float2*)&g_sigma[i0] = make_float2(sigx, sigy);
    *(float2*)&g_iv[i0]    = make_float2(1.f / (sigx * sigx + EPSV),
                                         1.f / (sigy * sigy + EPSV));
    float ls = logf(fabsf(sigx) + EPSV) + logf(fabsf(sigy) + EPSV);
#pragma unroll
    for (int o = 16; o > 0; o >>= 1) ls += __shfl_down_sync(0xFFFFFFFFu, ls, o);
    __shared__ float sh[4];
    int w = t >> 5, l = t & 31;
    if (l == 0) sh[w] = ls;
    __syncthreads();
    if (t == 0) {
        float tot = sh[0] + sh[1] + sh[2] + sh[3];
        g_cpart[bk * 2 + yh] = -0.25f * (float)Dd * LOG2PI - 0.5f * tot;
    }
}

// ------------------- merged outputs -----------------------------------------
__global__ void out_kernel(const float* __restrict__ noise_final,
                           float* __restrict__ out) {
    int t = threadIdx.x;               // 256
    if (blockIdx.x < Bsz * Kk) {       // slots: 128 blocks, 512 elems each
        int bk = blockIdx.x;
#pragma unroll
        for (int j = 0; j < 2; j++) {
            int i = bk * Dd + t + j * 256;
            float sg = fmaxf(fabsf(g_sigma[i]), EPSV);
            out[i] = g_mu[i] + sg * noise_final[i];
        }
    } else {                           // attn: 512 blocks
        int i = (blockIdx.x - Bsz * Kk) * 256 + t;     // 0..131071
        int n = i & (Nn - 1);
        int k = (i >> 10) & (Kk - 1);
        int b = i >> 13;
        out[Bsz * Kk * Dd + i] = g_attn[((size_t)(b * Nn + n)) * Kk + k]
                                 / (g_colsum[b * Kk + k] + EPSV);
    }
}

// ------------------- launch -------------------------------------------------
extern "C" void kernel_launch(void* const* d_in, const int* in_sizes, int n_in,
                              void* d_out, int out_size) {
    const float* embeddings  = (const float*)d_in[0];
    const float* noise_init  = (const float*)d_in[1];
    const float* noise_final = (const float*)d_in[2];
    const float* slots_mu    = (const float*)d_in[3];
    const float* slots_ls    = (const float*)d_in[4];
    const float* mixc        = (const float*)d_in[5];
    const float* Wk          = (const float*)d_in[6];
    const float* bk          = (const float*)d_in[7];
    const float* Wq          = (const float*)d_in[8];
    const float* bq          = (const float*)d_in[9];
    const float* Wv          = (const float*)d_in[10];
    const float* bv          = (const float*)d_in[11];
    const float* ln_g        = (const float*)d_in[12];
    const float* ln_b        = (const float*)d_in[13];
    float* out = (float*)d_out;

    cudaFuncSetAttribute(gemm_qinit_f16,
                         cudaFuncAttributeMaxDynamicSharedMemorySize, GEMM_SMEM);

    fused_pre_kernel<<<Bsz * Nn + 768, 256>>>(embeddings, Wk, Wv, Wq);    // 1
    gemm_qinit_f16<<<dim3(8, 128, 2), 256, GEMM_SMEM>>>(                  // 2
        embeddings, bk, bv, ln_g, ln_b,
        slots_mu, slots_ls, noise_init, bq, mixc);

    for (int it = 0; it < NITERS; it++) {
        gll_kernel<<<dim3(NCH, Bsz), 256>>>();                            // 3
        musig_part_kernel<<<dim3(SPLITS, Bsz), 256>>>();                  // 4 (profiled, it=0)
        musig_reduce_kernel<<<dim3(2, Bsz * Kk), 128>>>();
    }

    out_kernel<<<Bsz * Kk + (Bsz * Nn * Kk) / 256, 256>>>(noise_final, out);
}

// round 16
// speedup vs baseline: 1.1565x; 1.1565x over previous
#include <cuda_runtime.h>
#include <cuda_fp16.h>
#include <math.h>
#include <stdint.h>

#define Bsz 16
#define Nn 1024
#define Dd 512
#define Kk 8
#define NITERS 3
#define EPSV 1e-8f
#define LNEPS 1e-5f
#define LOG2PI 1.8378770664093453f
#define SPLITS 16
#define RPB (Nn / SPLITS)   // 64 rows per split block
#define GCH 32              // gll rows per chunk
#define NCH (Nn / GCH)      // 32 chunks

// ------------------- scratch (device globals, no runtime alloc) -------------
__device__ __half g_xh[Bsz * Nn * Dd];       // 16 MB (fp16 layer-normed input)
__device__ __half g_keysh[Bsz * Nn * Dd];    // 16 MB (fp16 keys)
__device__ __half g_valuesh[Bsz * Nn * Dd];  // 16 MB (fp16 values)
__device__ __half g_WTh[1024 * Dd];          // [Wk^T | Wv^T] as half
__device__ float g_WTq[Dd * Dd];             // Wq^T as float
__device__ float g_q[Bsz * Kk * Dd];
__device__ float g_sigma[Bsz * Kk * Dd];
__device__ float g_iv[Bsz * Kk * Dd];
__device__ float g_c[Bsz * Kk];
__device__ float g_mix[Bsz * Kk];
__device__ float g_attn[Bsz * Nn * Kk];      // row-normalized only
__device__ float g_colpart[Bsz * NCH * Kk];  // per-chunk partial colsums
__device__ float g_colsum[Bsz * Kk];
__device__ float g_snorm[Bsz * Kk];
__device__ float g_mu[Bsz * Kk * Dd];
__device__ __half g_parth[Bsz * SPLITS * Kk * Dd];   // 4 MB (fp16 partials)
__device__ __half g_part2h[Bsz * SPLITS * Kk * Dd];  // 4 MB

// ===== fused prologue: LN stats + normalize-to-fp16 + weight transposes =====
__global__ __launch_bounds__(256)
void fused_pre_kernel(const float* __restrict__ emb,
                      const float* __restrict__ Wk,
                      const float* __restrict__ Wv,
                      const float* __restrict__ Wq,
                      const float* __restrict__ ln_g,
                      const float* __restrict__ ln_b) {
    int t = threadIdx.x;
    if (blockIdx.x < Bsz * Nn) {
        int row = blockIdx.x;
        const float2* p = (const float2*)(emb + (size_t)row * Dd);
        float2 v = p[t];                      // 256 * 2 = 512
        float s  = v.x + v.y;
        float ss = v.x * v.x + v.y * v.y;
#pragma unroll
        for (int o = 16; o > 0; o >>= 1) {
            s  += __shfl_down_sync(0xFFFFFFFFu, s, o);
            ss += __shfl_down_sync(0xFFFFFFFFu, ss, o);
        }
        __shared__ float sh[16];
        __shared__ float s_m, s_r;
        int w = t >> 5, l = t & 31;
        if (l == 0) { sh[w] = s; sh[8 + w] = ss; }
        __syncthreads();
        if (t == 0) {
            s = 0.f; ss = 0.f;
            for (int i = 0; i < 8; i++) { s += sh[i]; ss += sh[8 + i]; }
            float m   = s / (float)Dd;
            float var = ss / (float)Dd - m * m;
            s_m = m;
            s_r = rsqrtf(var + LNEPS);
        }
        __syncthreads();
        float m = s_m, r = s_r;
        float2 gg = ((const float2*)ln_g)[t];
        float2 bb = ((const float2*)ln_b)[t];
        ((half2*)g_xh)[(size_t)row * (Dd / 2) + t] =
            __floats2half2_rn((v.x - m) * r * gg.x + bb.x,
                              (v.y - m) * r * gg.y + bb.y);
    } else {
        __shared__ float tt[32][33];
        int r = blockIdx.x - Bsz * Nn;        // 0..767
        int z = r >> 8;                       // 0..2
        int ry = (r >> 4) & 15, rx = r & 15;
        const float* W = (z == 0) ? Wk : (z == 1) ? Wv : Wq;
        int bx = rx * 32, by = ry * 32;
        int tx = t & 31, ty = t >> 5;         // 32 x 8
#pragma unroll
        for (int i = 0; i < 32; i += 8)
            tt[ty + i][tx] = W[(size_t)(by + ty + i) * Dd + bx + tx];
        __syncthreads();
        if (z < 2) {
            int nb = z * 512 + bx;
#pragma unroll
            for (int i = 0; i < 32; i += 8)
                g_WTh[(size_t)(nb + ty + i) * Dd + by + tx] = __float2half(tt[tx][ty + i]);
        } else {
#pragma unroll
            for (int i = 0; i < 32; i += 8)
                g_WTq[(size_t)(bx + ty + i) * Dd + by + tx] = tt[tx][ty + i];
        }
    }
}

// ------------------- fp16 GEMM (ldmatrix, fp16 A) + merged qinit ------------
#define GBM 128
#define GBN 128
#define GBK 32
#define LDH 40                       // 32 data halves + 8 pad (bank bijection)
#define TILEH (GBM * LDH)            // 5120 halves per buffer

__device__ __forceinline__ void mma_f16(float* c, const unsigned* a, const unsigned* b) {
    asm volatile(
        "mma.sync.aligned.m16n8k16.row.col.f32.f16.f16.f32 "
        "{%0,%1,%2,%3}, {%4,%5,%6,%7}, {%8,%9}, {%0,%1,%2,%3};"
        : "+f"(c[0]), "+f"(c[1]), "+f"(c[2]), "+f"(c[3])
        : "r"(a[0]), "r"(a[1]), "r"(a[2]), "r"(a[3]), "r"(b[0]), "r"(b[1]));
}
__device__ __forceinline__ void ldsm_x4(unsigned* r, uint32_t addr) {
    asm volatile("ldmatrix.sync.aligned.m8n8.x4.shared.b16 {%0,%1,%2,%3}, [%4];"
                 : "=r"(r[0]), "=r"(r[1]), "=r"(r[2]), "=r"(r[3]) : "r"(addr));
}

#define GEMM_SMEM (4 * TILEH * 2)    // 40960 bytes dynamic

// qinit body: executed by z=1 blocks (b = blockIdx.y>>3, by = blockIdx.y&7)
__device__ void qinit_body(char* smraw, int b, int by,
                           const float* __restrict__ mu_s,
                           const float* __restrict__ logsig,
                           const float* __restrict__ noise,
                           const float* __restrict__ bq,
                           const float* __restrict__ mixc) {
    float* s_sh  = (float*)smraw;          // Kk*Dd = 16 KB
    float* lg_sh = s_sh + Kk * Dd;         // 16 KB
    int t = threadIdx.x;                   // 256
    for (int i = t; i < Kk * Dd; i += 256) {
        float sg = expf(logsig[i]);
        float sl = mu_s[i] + sg * noise[b * Kk * Dd + i];
        s_sh[i] = sl;
        if (by == 0) {
            g_sigma[b * Kk * Dd + i] = sg;
            g_iv[b * Kk * Dd + i] = 1.f / (sg * sg + EPSV);
            lg_sh[i] = logf(fabsf(sg) + EPSV);
        }
    }
    if (by == 0 && t < Kk) g_mix[b * Kk + t] = mixc[t];
    __syncthreads();
    int w = t >> 5, lane = t & 31;
    if (by == 0) {
        float ls = 0.f;
#pragma unroll
        for (int j = 0; j < 16; j++) ls += lg_sh[w * Dd + lane + j * 32];
#pragma unroll
        for (int o = 16; o > 0; o >>= 1) ls += __shfl_down_sync(0xFFFFFFFFu, ls, o);
        if (lane == 0)
            g_c[b * Kk + w] = -0.5f * (float)Dd * LOG2PI - 0.5f * ls;
    }
#pragma unroll
    for (int jj = 0; jj < 8; jj++) {
        int j = by * 64 + w * 8 + jj;
        float acc[Kk];
#pragma unroll
        for (int k = 0; k < Kk; k++) acc[k] = 0.f;
#pragma unroll
        for (int i = 0; i < 4; i++) {
            float4 wq = *(const float4*)&g_WTq[(size_t)j * Dd + i * 128 + lane * 4];
#pragma unroll
            for (int k = 0; k < Kk; k++) {
                float4 s4 = *(const float4*)&s_sh[k * Dd + i * 128 + lane * 4];
                acc[k] += s4.x * wq.x + s4.y * wq.y + s4.z * wq.z + s4.w * wq.w;
            }
        }
#pragma unroll
        for (int o = 16; o > 0; o >>= 1)
#pragma unroll
            for (int k = 0; k < Kk; k++)
                acc[k] += __shfl_xor_sync(0xFFFFFFFFu, acc[k], o);
        if (lane < Kk) g_q[(b * Kk + lane) * Dd + j] = acc[lane] + bq[j];
    }
}

__global__ __launch_bounds__(256, 2)
void gemm_qinit_f16(const float* __restrict__ bk, const float* __restrict__ bv,
                    const float* __restrict__ mu_s,
                    const float* __restrict__ logsig,
                    const float* __restrict__ noise,
                    const float* __restrict__ bq,
                    const float* __restrict__ mixc) {
    extern __shared__ char smraw[];
    if (blockIdx.z == 1) {
        if (blockIdx.x != 0) return;       // only 128 of the z=1 blocks work
        qinit_body(smraw, (int)(blockIdx.y >> 3), (int)(blockIdx.y & 7),
                   mu_s, logsig, noise, bq, mixc);
        return;
    }
    __half* hs = (__half*)smraw;
    __half* Abuf[2] = { hs, hs + TILEH };
    __half* Bbuf[2] = { hs + 2 * TILEH, hs + 3 * TILEH };

    int tid = threadIdx.x;
    int bm = blockIdx.y * GBM;
    int bn = blockIdx.x * GBN;

    int lane = tid & 31, wrp = tid >> 5;
    int warpM = (wrp & 1) * 64, warpN = (wrp >> 1) * 32;
    int g = lane >> 2, ti = lane & 3;

    uint32_t sA[2] = { (uint32_t)__cvta_generic_to_shared(Abuf[0]),
                       (uint32_t)__cvta_generic_to_shared(Abuf[1]) };
    uint32_t sB[2] = { (uint32_t)__cvta_generic_to_shared(Bbuf[0]),
                       (uint32_t)__cvta_generic_to_shared(Bbuf[1]) };
    uint32_t aoff[4], boff[2];
#pragma unroll
    for (int mf = 0; mf < 4; mf++)
        aoff[mf] = ((warpM + mf * 16 + (lane & 15)) * LDH + ((lane >> 4) * 8)) * 2;
#pragma unroll
    for (int j = 0; j < 2; j++)
        boff[j] = ((warpN + j * 16 + (lane & 7) + ((lane >> 4) & 1) * 8) * LDH
                   + (((lane >> 3) & 1) * 8)) * 2;

    float acc[4][4][4];
#pragma unroll
    for (int mf = 0; mf < 4; mf++)
#pragma unroll
        for (int nf = 0; nf < 4; nf++)
#pragma unroll
            for (int c = 0; c < 4; c++) acc[mf][nf][c] = 0.f;

    uint4 paA[2], pw[2];

    // prologue: A (fp16 x_ln) and B tiles, each 2 x uint4 per thread
#pragma unroll
    for (int i = 0; i < 2; i++) {
        int idx = tid + i * 256;
        int m = idx >> 2, c8 = (idx & 3) * 8;
        paA[i] = *(const uint4*)&g_xh[(size_t)(bm + m) * Dd + c8];
        int n = idx >> 2;
        pw[i] = *(const uint4*)&g_WTh[(size_t)(bn + n) * Dd + c8];
    }
    {
#pragma unroll
        for (int i = 0; i < 2; i++) {
            int idx = tid + i * 256;
            int m = idx >> 2, c8 = (idx & 3) * 8;
            *(uint4*)&Abuf[0][m * LDH + c8] = paA[i];
            *(uint4*)&Bbuf[0][m * LDH + c8] = pw[i];
        }
    }
    __syncthreads();

    const int NSTEP = Dd / GBK;        // 16
    int p = 0;
    for (int step = 0; step < NSTEP; step++) {
        int k0n = (step + 1) * GBK;
        if (step + 1 < NSTEP) {
#pragma unroll
            for (int i = 0; i < 2; i++) {
                int idx = tid + i * 256;
                int m = idx >> 2, c8 = (idx & 3) * 8;
                paA[i] = *(const uint4*)&g_xh[(size_t)(bm + m) * Dd + k0n + c8];
                pw[i]  = *(const uint4*)&g_WTh[(size_t)(bn + m) * Dd + k0n + c8];
            }
        }
#pragma unroll
        for (int ks = 0; ks < 2; ks++) {
            uint32_t kboff = ks * 32;  // 16 halves = 32 bytes
            unsigned afr[4][4], bfr[4][2];
#pragma unroll
            for (int mf = 0; mf < 4; mf++)
                ldsm_x4(afr[mf], sA[p] + aoff[mf] + kboff);
            {
                unsigned bq0[4], bq1[4];
                ldsm_x4(bq0, sB[p] + boff[0] + kboff);
                ldsm_x4(bq1, sB[p] + boff[1] + kboff);
                bfr[0][0] = bq0[0]; bfr[0][1] = bq0[1];
                bfr[1][0] = bq0[2]; bfr[1][1] = bq0[3];
                bfr[2][0] = bq1[0]; bfr[2][1] = bq1[1];
                bfr[3][0] = bq1[2]; bfr[3][1] = bq1[3];
            }
#pragma unroll
            for (int mf = 0; mf < 4; mf++)
#pragma unroll
                for (int nf = 0; nf < 4; nf++)
                    mma_f16(acc[mf][nf], afr[mf], bfr[nf]);
        }
        if (step + 1 < NSTEP) {
            int np = p ^ 1;
            __syncthreads();
#pragma unroll
            for (int i = 0; i < 2; i++) {
                int idx = tid + i * 256;
                int m = idx >> 2, c8 = (idx & 3) * 8;
                *(uint4*)&Abuf[np][m * LDH + c8] = paA[i];
                *(uint4*)&Bbuf[np][m * LDH + c8] = pw[i];
            }
            __syncthreads();
            p = np;
        }
    }

    // epilogue: keys & values both fp16
    int coloff = bn & (Dd - 1);
    __half* Cout = (bn < Dd) ? g_keysh : g_valuesh;
    const float* bias = (bn < Dd) ? bk : bv;
#pragma unroll
    for (int mf = 0; mf < 4; mf++) {
        int row = bm + warpM + mf * 16 + g;
#pragma unroll
        for (int nf = 0; nf < 4; nf++) {
            int col = coloff + warpN + nf * 8 + 2 * ti;
            float b0 = bias[col], b1 = bias[col + 1];
            *(__half2*)&Cout[(size_t)row * Dd + col] =
                __floats2half2_rn(acc[mf][nf][0] + b0, acc[mf][nf][1] + b1);
            *(__half2*)&Cout[(size_t)(row + 8) * Dd + col] =
                __floats2half2_rn(acc[mf][nf][2] + b0, acc[mf][nf][3] + b1);
        }
    }
}

// ---- gll: warp = one slot k, fp16 keys, 32-row chunks ----------------------
__global__ __launch_bounds__(256)
void gll_kernel() {
    int b = blockIdx.y;
    int chunk = blockIdx.x;            // 32 chunks of 32 rows
    int t = threadIdx.x;               // 256 = 8 warps = 8 slots
    int k = t >> 5, lane = t & 31;
    __shared__ float gll_sh[Kk][36];   // padded

    float4 qr[4], ivr[4];
    size_t tb = (size_t)(b * Kk + k) * Dd;
    int d0 = lane * 8;
#pragma unroll
    for (int h = 0; h < 2; h++)
#pragma unroll
        for (int j = 0; j < 2; j++) {
            qr[h * 2 + j]  = *(const float4*)&g_q[tb + h * 256 + d0 + j * 4];
            ivr[h * 2 + j] = *(const float4*)&g_iv[tb + h * 256 + d0 + j * 4];
        }
    float cc = g_c[b * Kk + k], mx = g_mix[b * Kk + k];
    int nbase = chunk * GCH;
    const __half* kb = g_keysh + ((size_t)(b * Nn + nbase)) * Dd;

#pragma unroll 4
    for (int r = 0; r < GCH; r++) {
        const uint4* kr = (const uint4*)(kb + (size_t)r * Dd);
        uint4 p0 = kr[lane];
        uint4 p1 = kr[32 + lane];
        float s = 0.f;
        const __half2* h0 = (const __half2*)&p0;
        const __half2* h1 = (const __half2*)&p1;
#pragma unroll
        for (int j = 0; j < 2; j++) {
            float2 a0 = __half22float2(h0[j * 2]);
            float2 a1 = __half22float2(h0[j * 2 + 1]);
            float dx = a0.x - qr[j].x, dy = a0.y - qr[j].y;
            float dz = a1.x - qr[j].z, dw = a1.y - qr[j].w;
            s += dx * dx * ivr[j].x + dy * dy * ivr[j].y
               + dz * dz * ivr[j].z + dw * dw * ivr[j].w;
            float2 b0 = __half22float2(h1[j * 2]);
            float2 b1 = __half22float2(h1[j * 2 + 1]);
            float ex = b0.x - qr[2 + j].x, ey = b0.y - qr[2 + j].y;
            float ez = b1.x - qr[2 + j].z, ew = b1.y - qr[2 + j].w;
            s += ex * ex * ivr[2 + j].x + ey * ey * ivr[2 + j].y
               + ez * ez * ivr[2 + j].z + ew * ew * ivr[2 + j].w;
        }
#pragma unroll
        for (int o = 16; o > 0; o >>= 1) s += __shfl_xor_sync(0xFFFFFFFFu, s, o);
        if (lane == 0) gll_sh[k][r] = mx * (cc - 0.5f * s);
    }
    __syncthreads();

    if (t < GCH) {
        float v[Kk], rs = 0.f;
#pragma unroll
        for (int kk = 0; kk < Kk; kk++) { v[kk] = gll_sh[kk][t]; rs += v[kk]; }
        float inv = 1.f / rs;
        float a[Kk];
#pragma unroll
        for (int kk = 0; kk < Kk; kk++) a[kk] = v[kk] * inv;
        float* ap = g_attn + ((size_t)(b * Nn + nbase + t)) * Kk;
        float4 o0 = { a[0], a[1], a[2], a[3] };
        float4 o1 = { a[4], a[5], a[6], a[7] };
        *(float4*)ap = o0;
        *(float4*)(ap + 4) = o1;
#pragma unroll
        for (int o = 16; o > 0; o >>= 1)
#pragma unroll
            for (int kk = 0; kk < Kk; kk++)
                a[kk] += __shfl_xor_sync(0xFFFFFFFFu, a[kk], o);
        if (t == 0)
#pragma unroll
            for (int kk = 0; kk < Kk; kk++)
                g_colpart[(b * NCH + chunk) * Kk + kk] = a[kk];
    }
}

// ------ fused mu & sigma partials + in-block colsum (fp16 partial stores) ---
__global__ __launch_bounds__(256)
void musig_part_kernel() {
    int b = blockIdx.y, s = blockIdx.x;
    __shared__ float a_sh[RPB][Kk];    // 2 KB
    __shared__ float cs_sh[Kk];
    int t = threadIdx.x;               // 256; owns cols 2t, 2t+1
    if (t < Kk) {
        float tot = 0.f;
#pragma unroll
        for (int c = 0; c < NCH; c++) tot += g_colpart[(b * NCH + c) * Kk + t];
        cs_sh[t] = tot + EPSV;
        if (s == 0) {
            g_colsum[b * Kk + t] = tot;
            float sf = tot / (tot + EPSV);
            g_snorm[b * Kk + t] = sf;
            g_mix[b * Kk + t] = sf / (float)Nn;   // for next iteration's gll
        }
    }
    __syncthreads();
    for (int i = t; i < RPB * Kk; i += 256)
        a_sh[i >> 3][i & 7] = g_attn[((size_t)(b * Nn + s * RPB)) * Kk + i]
                              / cs_sh[i & 7];
    __syncthreads();
    float acc1x[Kk], acc1y[Kk], acc2x[Kk], acc2y[Kk];
#pragma unroll
    for (int k = 0; k < Kk; k++) {
        acc1x[k] = 0.f; acc1y[k] = 0.f; acc2x[k] = 0.f; acc2y[k] = 0.f;
    }
    const __half2* vb = (const __half2*)(g_valuesh
                        + ((size_t)(b * Nn + s * RPB)) * Dd) + t;
    for (int r = 0; r < RPB; r += 2) {
        float2 v0 = __half22float2(vb[(size_t)r * (Dd / 2)]);
        float2 v1 = __half22float2(vb[(size_t)(r + 1) * (Dd / 2)]);
#pragma unroll
        for (int k = 0; k < Kk; k++) {
            float a0 = a_sh[r][k], a1 = a_sh[r + 1][k];
            acc1x[k] += a0 * v0.x + a1 * v1.x;
            acc1y[k] += a0 * v0.y + a1 * v1.y;
            acc2x[k] += a0 * v0.x * v0.x + a1 * v1.x * v1.x;
            acc2y[k] += a0 * v0.y * v0.y + a1 * v1.y * v1.y;
        }
    }
#pragma unroll
    for (int k = 0; k < Kk; k++) {
        size_t idx = (((size_t)b * SPLITS + s) * Kk + k) * (Dd / 2) + t;
        ((__half2*)g_parth)[idx]  = __floats2half2_rn(acc1x[k], acc1y[k]);
        ((__half2*)g_part2h)[idx] = __floats2half2_rn(acc2x[k], acc2y[k]);
    }
}

// reduce: mu = sum parts; sigma = q2 - (2 - S) mu^2; fused next-iter prep ----
__global__ __launch_bounds__(256)
void musig_reduce_kernel() {
    int bk = blockIdx.x;
    int b = bk >> 3, k = bk & 7;
    int t = threadIdx.x;               // 256; owns cols 2t, 2t+1
    float mx = 0.f, my = 0.f, q2x = 0.f, q2y = 0.f;
#pragma unroll 8
    for (int s = 0; s < SPLITS; s++) {
        size_t idx = (((size_t)b * SPLITS + s) * Kk + k) * (Dd / 2) + t;
        float2 p1 = __half22float2(((const __half2*)g_parth)[idx]);
        float2 p2 = __half22float2(((const __half2*)g_part2h)[idx]);
        mx += p1.x; my += p1.y;
        q2x += p2.x; q2y += p2.y;
    }
    float sfac = g_snorm[bk];
    float sigx = q2x - (2.f - sfac) * mx * mx;
    float sigy = q2y - (2.f - sfac) * my * my;
    int i0 = bk * Dd + 2 * t;
    *(float2*)&g_mu[i0]    = make_float2(mx, my);
    *(float2*)&g_sigma[i0] = make_float2(sigx, sigy);
    *(float2*)&g_iv[i0]    = make_float2(1.f / (sigx * sigx + EPSV),
                                         1.f / (sigy * sigy + EPSV));
    float ls = logf(fabsf(sigx) + EPSV) + logf(fabsf(sigy) + EPSV);
#pragma unroll
    for (int o = 16; o > 0; o >>= 1) ls += __shfl_down_sync(0xFFFFFFFFu, ls, o);
    __shared__ float sh[8];
    int w = t >> 5, l = t & 31;
    if (l == 0) sh[w] = ls;
    __syncthreads();
    if (t == 0) {
        float tot = 0.f;
        for (int i = 0; i < 8; i++) tot += sh[i];
        g_c[bk] = -0.5f * (float)Dd * LOG2PI - 0.5f * tot;
    }
}

// ------------------- merged outputs -----------------------------------------
__global__ void out_kernel(const float* __restrict__ noise_final,
                           float* __restrict__ out) {
    int t = threadIdx.x;               // 256
    if (blockIdx.x < Bsz * Kk) {       // slots: 128 blocks, 512 elems each
        int bk = blockIdx.x;
#pragma unroll
        for (int j = 0; j < 2; j++) {
            int i = bk * Dd + t + j * 256;
            float sg = fmaxf(fabsf(g_sigma[i]), EPSV);
            out[i] = g_mu[i] + sg * noise_final[i];
        }
    } else {                           // attn: 512 blocks
        int i = (blockIdx.x - Bsz * Kk) * 256 + t;     // 0..131071
        int n = i & (Nn - 1);
        int k = (i >> 10) & (Kk - 1);
        int b = i >> 13;
        out[Bsz * Kk * Dd + i] = g_attn[((size_t)(b * Nn + n)) * Kk + k]
                                 / (g_colsum[b * Kk + k] + EPSV);
    }
}

// ------------------- launch -------------------------------------------------
extern "C" void kernel_launch(void* const* d_in, const int* in_sizes, int n_in,
                              void* d_out, int out_size) {
    const float* embeddings  = (const float*)d_in[0];
    const float* noise_init  = (const float*)d_in[1];
    const float* noise_final = (const float*)d_in[2];
    const float* slots_mu    = (const float*)d_in[3];
    const float* slots_ls    = (const float*)d_in[4];
    const float* mixc        = (const float*)d_in[5];
    const float* Wk          = (const float*)d_in[6];
    const float* bk          = (const float*)d_in[7];
    const float* Wq          = (const float*)d_in[8];
    const float* bq          = (const float*)d_in[9];
    const float* Wv          = (const float*)d_in[10];
    const float* bv          = (const float*)d_in[11];
    const float* ln_g        = (const float*)d_in[12];
    const float* ln_b        = (const float*)d_in[13];
    float* out = (float*)d_out;

    cudaFuncSetAttribute(gemm_qinit_f16,
                         cudaFuncAttributeMaxDynamicSharedMemorySize, GEMM_SMEM);

    fused_pre_kernel<<<Bsz * Nn + 768, 256>>>(embeddings, Wk, Wv, Wq,     // 1
                                              ln_g, ln_b);
    gemm_qinit_f16<<<dim3(8, 128, 2), 256, GEMM_SMEM>>>(                  // 2
        bk, bv, slots_mu, slots_ls, noise_init, bq, mixc);

    for (int it = 0; it < NITERS; it++) {
        gll_kernel<<<dim3(NCH, Bsz), 256>>>();                            // 3
        musig_part_kernel<<<dim3(SPLITS, Bsz), 256>>>();                  // 4 (profiled, it=0)
        musig_reduce_kernel<<<Bsz * Kk, 256>>>();
    }

    out_kernel<<<Bsz * Kk + (Bsz * Nn * Kk) / 256, 256>>>(noise_final, out);
}

// round 17
// speedup vs baseline: 1.1679x; 1.0099x over previous
#include <cuda_runtime.h>
#include <cuda_fp16.h>
#include <math.h>
#include <stdint.h>

#define Bsz 16
#define Nn 1024
#define Dd 512
#define Kk 8
#define NITERS 3
#define EPSV 1e-8f
#define LNEPS 1e-5f
#define LOG2PI 1.8378770664093453f
#define SPLITS 16
#define RPB (Nn / SPLITS)   // 64 rows per split block
#define GCH 32              // gll rows per chunk
#define NCH (Nn / GCH)      // 32 chunks

// ------------------- scratch (device globals, no runtime alloc) -------------
__device__ __half g_xh[Bsz * Nn * Dd];       // 16 MB (fp16 layer-normed input)
__device__ __half g_keysh[Bsz * Nn * Dd];    // 16 MB (fp16 keys)
__device__ __half g_valuesh[Bsz * Nn * Dd];  // 16 MB (fp16 values)
__device__ __half g_WTh[1024 * Dd];          // [Wk^T | Wv^T] as half
__device__ float g_WTq[Dd * Dd];             // Wq^T as float
__device__ float g_q[Bsz * Kk * Dd];
__device__ float g_sigma[Bsz * Kk * Dd];
__device__ float g_iv[Bsz * Kk * Dd];
__device__ float g_c[Bsz * Kk];
__device__ float g_mix[Bsz * Kk];
__device__ float g_attn[Bsz * Nn * Kk];      // row-normalized only
__device__ float g_colpart[Bsz * NCH * Kk];  // per-chunk partial colsums
__device__ float g_colsum[Bsz * Kk];
__device__ float g_snorm[Bsz * Kk];
__device__ float g_mu[Bsz * Kk * Dd];
__device__ __half g_parth[Bsz * SPLITS * Kk * Dd];   // 4 MB (fp16 partials)
__device__ __half g_part2h[Bsz * SPLITS * Kk * Dd];  // 4 MB

// ===== fused prologue: LN stats + normalize-to-fp16 + weight transposes =====
__global__ __launch_bounds__(256)
void fused_pre_kernel(const float* __restrict__ emb,
                      const float* __restrict__ Wk,
                      const float* __restrict__ Wv,
                      const float* __restrict__ Wq,
                      const float* __restrict__ ln_g,
                      const float* __restrict__ ln_b) {
    int t = threadIdx.x;
    if (blockIdx.x < Bsz * Nn) {
        int row = blockIdx.x;
        const float2* p = (const float2*)(emb + (size_t)row * Dd);
        float2 v = p[t];                      // 256 * 2 = 512
        float s  = v.x + v.y;
        float ss = v.x * v.x + v.y * v.y;
#pragma unroll
        for (int o = 16; o > 0; o >>= 1) {
            s  += __shfl_down_sync(0xFFFFFFFFu, s, o);
            ss += __shfl_down_sync(0xFFFFFFFFu, ss, o);
        }
        __shared__ float sh[16];
        __shared__ float s_m, s_r;
        int w = t >> 5, l = t & 31;
        if (l == 0) { sh[w] = s; sh[8 + w] = ss; }
        __syncthreads();
        if (t == 0) {
            s = 0.f; ss = 0.f;
            for (int i = 0; i < 8; i++) { s += sh[i]; ss += sh[8 + i]; }
            float m   = s / (float)Dd;
            float var = ss / (float)Dd - m * m;
            s_m = m;
            s_r = rsqrtf(var + LNEPS);
        }
        __syncthreads();
        float m = s_m, r = s_r;
        float2 gg = ((const float2*)ln_g)[t];
        float2 bb = ((const float2*)ln_b)[t];
        ((half2*)g_xh)[(size_t)row * (Dd / 2) + t] =
            __floats2half2_rn((v.x - m) * r * gg.x + bb.x,
                              (v.y - m) * r * gg.y + bb.y);
    } else {
        __shared__ float tt[32][33];
        int r = blockIdx.x - Bsz * Nn;        // 0..767
        int z = r >> 8;                       // 0..2
        int ry = (r >> 4) & 15, rx = r & 15;
        const float* W = (z == 0) ? Wk : (z == 1) ? Wv : Wq;
        int bx = rx * 32, by = ry * 32;
        int tx = t & 31, ty = t >> 5;         // 32 x 8
#pragma unroll
        for (int i = 0; i < 32; i += 8)
            tt[ty + i][tx] = W[(size_t)(by + ty + i) * Dd + bx + tx];
        __syncthreads();
        if (z < 2) {
            int nb = z * 512 + bx;
#pragma unroll
            for (int i = 0; i < 32; i += 8)
                g_WTh[(size_t)(nb + ty + i) * Dd + by + tx] = __float2half(tt[tx][ty + i]);
        } else {
#pragma unroll
            for (int i = 0; i < 32; i += 8)
                g_WTq[(size_t)(bx + ty + i) * Dd + by + tx] = tt[tx][ty + i];
        }
    }
}

// ------------------- fp16 GEMM (ldmatrix, fp16 A) + merged qinit ------------
#define GBM 128
#define GBN 128
#define GBK 32
#define LDH 40                       // 32 data halves + 8 pad (bank bijection)
#define TILEH (GBM * LDH)            // 5120 halves per buffer

__device__ __forceinline__ void mma_f16(float* c, const unsigned* a, const unsigned* b) {
    asm volatile(
        "mma.sync.aligned.m16n8k16.row.col.f32.f16.f16.f32 "
        "{%0,%1,%2,%3}, {%4,%5,%6,%7}, {%8,%9}, {%0,%1,%2,%3};"
        : "+f"(c[0]), "+f"(c[1]), "+f"(c[2]), "+f"(c[3])
        : "r"(a[0]), "r"(a[1]), "r"(a[2]), "r"(a[3]), "r"(b[0]), "r"(b[1]));
}
__device__ __forceinline__ void ldsm_x4(unsigned* r, uint32_t addr) {
    asm volatile("ldmatrix.sync.aligned.m8n8.x4.shared.b16 {%0,%1,%2,%3}, [%4];"
                 : "=r"(r[0]), "=r"(r[1]), "=r"(r[2]), "=r"(r[3]) : "r"(addr));
}

#define GEMM_SMEM (4 * TILEH * 2)    // 40960 bytes dynamic

// qinit body: executed by z=1 blocks (b = blockIdx.y>>3, by = blockIdx.y&7)
__device__ void qinit_body(char* smraw, int b, int by,
                           const float* __restrict__ mu_s,
                           const float* __restrict__ logsig,
                           const float* __restrict__ noise,
                           const float* __restrict__ bq,
                           const float* __restrict__ mixc) {
    float* s_sh  = (float*)smraw;          // Kk*Dd = 16 KB
    float* lg_sh = s_sh + Kk * Dd;         // 16 KB
    int t = threadIdx.x;                   // 256
    for (int i = t; i < Kk * Dd; i += 256) {
        float sg = expf(logsig[i]);
        float sl = mu_s[i] + sg * noise[b * Kk * Dd + i];
        s_sh[i] = sl;
        if (by == 0) {
            g_sigma[b * Kk * Dd + i] = sg;
            g_iv[b * Kk * Dd + i] = 1.f / (sg * sg + EPSV);
            lg_sh[i] = logf(fabsf(sg) + EPSV);
        }
    }
    if (by == 0 && t < Kk) g_mix[b * Kk + t] = mixc[t];
    __syncthreads();
    int w = t >> 5, lane = t & 31;
    if (by == 0) {
        float ls = 0.f;
#pragma unroll
        for (int j = 0; j < 16; j++) ls += lg_sh[w * Dd + lane + j * 32];
#pragma unroll
        for (int o = 16; o > 0; o >>= 1) ls += __shfl_down_sync(0xFFFFFFFFu, ls, o);
        if (lane == 0)
            g_c[b * Kk + w] = -0.5f * (float)Dd * LOG2PI - 0.5f * ls;
    }
#pragma unroll
    for (int jj = 0; jj < 8; jj++) {
        int j = by * 64 + w * 8 + jj;
        float acc[Kk];
#pragma unroll
        for (int k = 0; k < Kk; k++) acc[k] = 0.f;
#pragma unroll
        for (int i = 0; i < 4; i++) {
            float4 wq = *(const float4*)&g_WTq[(size_t)j * Dd + i * 128 + lane * 4];
#pragma unroll
            for (int k = 0; k < Kk; k++) {
                float4 s4 = *(const float4*)&s_sh[k * Dd + i * 128 + lane * 4];
                acc[k] += s4.x * wq.x + s4.y * wq.y + s4.z * wq.z + s4.w * wq.w;
            }
        }
#pragma unroll
        for (int o = 16; o > 0; o >>= 1)
#pragma unroll
            for (int k = 0; k < Kk; k++)
                acc[k] += __shfl_xor_sync(0xFFFFFFFFu, acc[k], o);
        if (lane < Kk) g_q[(b * Kk + lane) * Dd + j] = acc[lane] + bq[j];
    }
}

__global__ __launch_bounds__(256, 2)
void gemm_qinit_f16(const float* __restrict__ bk, const float* __restrict__ bv,
                    const float* __restrict__ mu_s,
                    const float* __restrict__ logsig,
                    const float* __restrict__ noise,
                    const float* __restrict__ bq,
                    const float* __restrict__ mixc) {
    extern __shared__ char smraw[];
    if (blockIdx.z == 1) {
        if (blockIdx.x != 0) return;       // only 128 of the z=1 blocks work
        qinit_body(smraw, (int)(blockIdx.y >> 3), (int)(blockIdx.y & 7),
                   mu_s, logsig, noise, bq, mixc);
        return;
    }
    __half* hs = (__half*)smraw;
    __half* Abuf[2] = { hs, hs + TILEH };
    __half* Bbuf[2] = { hs + 2 * TILEH, hs + 3 * TILEH };

    int tid = threadIdx.x;
    int bm = blockIdx.y * GBM;
    int bn = blockIdx.x * GBN;

    int lane = tid & 31, wrp = tid >> 5;
    int warpM = (wrp & 1) * 64, warpN = (wrp >> 1) * 32;
    int g = lane >> 2, ti = lane & 3;

    uint32_t sA[2] = { (uint32_t)__cvta_generic_to_shared(Abuf[0]),
                       (uint32_t)__cvta_generic_to_shared(Abuf[1]) };
    uint32_t sB[2] = { (uint32_t)__cvta_generic_to_shared(Bbuf[0]),
                       (uint32_t)__cvta_generic_to_shared(Bbuf[1]) };
    uint32_t aoff[4], boff[2];
#pragma unroll
    for (int mf = 0; mf < 4; mf++)
        aoff[mf] = ((warpM + mf * 16 + (lane & 15)) * LDH + ((lane >> 4) * 8)) * 2;
#pragma unroll
    for (int j = 0; j < 2; j++)
        boff[j] = ((warpN + j * 16 + (lane & 7) + ((lane >> 4) & 1) * 8) * LDH
                   + (((lane >> 3) & 1) * 8)) * 2;

    float acc[4][4][4];
#pragma unroll
    for (int mf = 0; mf < 4; mf++)
#pragma unroll
        for (int nf = 0; nf < 4; nf++)
#pragma unroll
            for (int c = 0; c < 4; c++) acc[mf][nf][c] = 0.f;

    uint4 paA[2], pw[2];

    // prologue: A (fp16 x_ln) and B tiles, each 2 x uint4 per thread
#pragma unroll
    for (int i = 0; i < 2; i++) {
        int idx = tid + i * 256;
        int m = idx >> 2, c8 = (idx & 3) * 8;
        paA[i] = *(const uint4*)&g_xh[(size_t)(bm + m) * Dd + c8];
        pw[i]  = *(const uint4*)&g_WTh[(size_t)(bn + m) * Dd + c8];
    }
    {
#pragma unroll
        for (int i = 0; i < 2; i++) {
            int idx = tid + i * 256;
            int m = idx >> 2, c8 = (idx & 3) * 8;
            *(uint4*)&Abuf[0][m * LDH + c8] = paA[i];
            *(uint4*)&Bbuf[0][m * LDH + c8] = pw[i];
        }
    }
    __syncthreads();

    const int NSTEP = Dd / GBK;        // 16
    int p = 0;
    for (int step = 0; step < NSTEP; step++) {
        int k0n = (step + 1) * GBK;
        if (step + 1 < NSTEP) {
#pragma unroll
            for (int i = 0; i < 2; i++) {
                int idx = tid + i * 256;
                int m = idx >> 2, c8 = (idx & 3) * 8;
                paA[i] = *(const uint4*)&g_xh[(size_t)(bm + m) * Dd + k0n + c8];
                pw[i]  = *(const uint4*)&g_WTh[(size_t)(bn + m) * Dd + k0n + c8];
            }
        }
#pragma unroll
        for (int ks = 0; ks < 2; ks++) {
            uint32_t kboff = ks * 32;  // 16 halves = 32 bytes
            unsigned afr[4][4], bfr[4][2];
#pragma unroll
            for (int mf = 0; mf < 4; mf++)
                ldsm_x4(afr[mf], sA[p] + aoff[mf] + kboff);
            {
                unsigned bq0[4], bq1[4];
                ldsm_x4(bq0, sB[p] + boff[0] + kboff);
                ldsm_x4(bq1, sB[p] + boff[1] + kboff);
                bfr[0][0] = bq0[0]; bfr[0][1] = bq0[1];
                bfr[1][0] = bq0[2]; bfr[1][1] = bq0[3];
                bfr[2][0] = bq1[0]; bfr[2][1] = bq1[1];
                bfr[3][0] = bq1[2]; bfr[3][1] = bq1[3];
            }
#pragma unroll
            for (int mf = 0; mf < 4; mf++)
#pragma unroll
                for (int nf = 0; nf < 4; nf++)
                    mma_f16(acc[mf][nf], afr[mf], bfr[nf]);
        }
        if (step + 1 < NSTEP) {
            int np = p ^ 1;
            __syncthreads();
#pragma unroll
            for (int i = 0; i < 2; i++) {
                int idx = tid + i * 256;
                int m = idx >> 2, c8 = (idx & 3) * 8;
                *(uint4*)&Abuf[np][m * LDH + c8] = paA[i];
                *(uint4*)&Bbuf[np][m * LDH + c8] = pw[i];
            }
            __syncthreads();
            p = np;
        }
    }

    // epilogue: keys & values both fp16
    int coloff = bn & (Dd - 1);
    __half* Cout = (bn < Dd) ? g_keysh : g_valuesh;
    const float* bias = (bn < Dd) ? bk : bv;
#pragma unroll
    for (int mf = 0; mf < 4; mf++) {
        int row = bm + warpM + mf * 16 + g;
#pragma unroll
        for (int nf = 0; nf < 4; nf++) {
            int col = coloff + warpN + nf * 8 + 2 * ti;
            float b0 = bias[col], b1 = bias[col + 1];
            *(__half2*)&Cout[(size_t)row * Dd + col] =
                __floats2half2_rn(acc[mf][nf][0] + b0, acc[mf][nf][1] + b1);
            *(__half2*)&Cout[(size_t)(row + 8) * Dd + col] =
                __floats2half2_rn(acc[mf][nf][2] + b0, acc[mf][nf][3] + b1);
        }
    }
}

// ---- gll: warp = one slot k, fp16 keys, 32-row chunks ----------------------
__global__ __launch_bounds__(256)
void gll_kernel() {
    int b = blockIdx.y;
    int chunk = blockIdx.x;            // 32 chunks of 32 rows
    int t = threadIdx.x;               // 256 = 8 warps = 8 slots
    int k = t >> 5, lane = t & 31;
    __shared__ float gll_sh[Kk][36];   // padded

    float4 qr[4], ivr[4];
    size_t tb = (size_t)(b * Kk + k) * Dd;
    int d0 = lane * 8;
#pragma unroll
    for (int h = 0; h < 2; h++)
#pragma unroll
        for (int j = 0; j < 2; j++) {
            qr[h * 2 + j]  = *(const float4*)&g_q[tb + h * 256 + d0 + j * 4];
            ivr[h * 2 + j] = *(const float4*)&g_iv[tb + h * 256 + d0 + j * 4];
        }
    float cc = g_c[b * Kk + k], mx = g_mix[b * Kk + k];
    int nbase = chunk * GCH;
    const __half* kb = g_keysh + ((size_t)(b * Nn + nbase)) * Dd;

#pragma unroll 4
    for (int r = 0; r < GCH; r++) {
        const uint4* kr = (const uint4*)(kb + (size_t)r * Dd);
        uint4 p0 = kr[lane];
        uint4 p1 = kr[32 + lane];
        float s = 0.f;
        const __half2* h0 = (const __half2*)&p0;
        const __half2* h1 = (const __half2*)&p1;
#pragma unroll
        for (int j = 0; j < 2; j++) {
            float2 a0 = __half22float2(h0[j * 2]);
            float2 a1 = __half22float2(h0[j * 2 + 1]);
            float dx = a0.x - qr[j].x, dy = a0.y - qr[j].y;
            float dz = a1.x - qr[j].z, dw = a1.y - qr[j].w;
            s += dx * dx * ivr[j].x + dy * dy * ivr[j].y
               + dz * dz * ivr[j].z + dw * dw * ivr[j].w;
            float2 b0 = __half22float2(h1[j * 2]);
            float2 b1 = __half22float2(h1[j * 2 + 1]);
            float ex = b0.x - qr[2 + j].x, ey = b0.y - qr[2 + j].y;
            float ez = b1.x - qr[2 + j].z, ew = b1.y - qr[2 + j].w;
            s += ex * ex * ivr[2 + j].x + ey * ey * ivr[2 + j].y
               + ez * ez * ivr[2 + j].z + ew * ew * ivr[2 + j].w;
        }
#pragma unroll
        for (int o = 16; o > 0; o >>= 1) s += __shfl_xor_sync(0xFFFFFFFFu, s, o);
        if (lane == 0) gll_sh[k][r] = mx * (cc - 0.5f * s);
    }
    __syncthreads();

    if (t < GCH) {
        float v[Kk], rs = 0.f;
#pragma unroll
        for (int kk = 0; kk < Kk; kk++) { v[kk] = gll_sh[kk][t]; rs += v[kk]; }
        float inv = 1.f / rs;
        float a[Kk];
#pragma unroll
        for (int kk = 0; kk < Kk; kk++) a[kk] = v[kk] * inv;
        float* ap = g_attn + ((size_t)(b * Nn + nbase + t)) * Kk;
        float4 o0 = { a[0], a[1], a[2], a[3] };
        float4 o1 = { a[4], a[5], a[6], a[7] };
        *(float4*)ap = o0;
        *(float4*)(ap + 4) = o1;
#pragma unroll
        for (int o = 16; o > 0; o >>= 1)
#pragma unroll
            for (int kk = 0; kk < Kk; kk++)
                a[kk] += __shfl_xor_sync(0xFFFFFFFFu, a[kk], o);
        if (t == 0)
#pragma unroll
            for (int kk = 0; kk < Kk; kk++)
                g_colpart[(b * NCH + chunk) * Kk + kk] = a[kk];
    }
}

// ------ fused mu & sigma partials + in-block colsum (unroll-4 loads) --------
__global__ __launch_bounds__(256)
void musig_part_kernel() {
    int b = blockIdx.y, s = blockIdx.x;
    __shared__ float a_sh[RPB][Kk];    // 2 KB
    __shared__ float cs_sh[Kk];
    int t = threadIdx.x;               // 256; owns cols 2t, 2t+1
    if (t < Kk) {
        float tot = 0.f;
#pragma unroll
        for (int c = 0; c < NCH; c++) tot += g_colpart[(b * NCH + c) * Kk + t];
        cs_sh[t] = tot + EPSV;
        if (s == 0) {
            g_colsum[b * Kk + t] = tot;
            float sf = tot / (tot + EPSV);
            g_snorm[b * Kk + t] = sf;
            g_mix[b * Kk + t] = sf / (float)Nn;   // for next iteration's gll
        }
    }
    __syncthreads();
    for (int i = t; i < RPB * Kk; i += 256)
        a_sh[i >> 3][i & 7] = g_attn[((size_t)(b * Nn + s * RPB)) * Kk + i]
                              / cs_sh[i & 7];
    __syncthreads();
    float acc1x[Kk], acc1y[Kk], acc2x[Kk], acc2y[Kk];
#pragma unroll
    for (int k = 0; k < Kk; k++) {
        acc1x[k] = 0.f; acc1y[k] = 0.f; acc2x[k] = 0.f; acc2y[k] = 0.f;
    }
    const __half2* vb = (const __half2*)(g_valuesh
                        + ((size_t)(b * Nn + s * RPB)) * Dd) + t;
    for (int r = 0; r < RPB; r += 4) {
        float2 v0 = __half22float2(vb[(size_t)(r + 0) * (Dd / 2)]);
        float2 v1 = __half22float2(vb[(size_t)(r + 1) * (Dd / 2)]);
        float2 v2 = __half22float2(vb[(size_t)(r + 2) * (Dd / 2)]);
        float2 v3 = __half22float2(vb[(size_t)(r + 3) * (Dd / 2)]);
#pragma unroll
        for (int k = 0; k < Kk; k++) {
            float a0 = a_sh[r][k], a1 = a_sh[r + 1][k];
            float a2 = a_sh[r + 2][k], a3 = a_sh[r + 3][k];
            acc1x[k] += a0 * v0.x + a1 * v1.x + a2 * v2.x + a3 * v3.x;
            acc1y[k] += a0 * v0.y + a1 * v1.y + a2 * v2.y + a3 * v3.y;
            acc2x[k] += a0 * v0.x * v0.x + a1 * v1.x * v1.x
                      + a2 * v2.x * v2.x + a3 * v3.x * v3.x;
            acc2y[k] += a0 * v0.y * v0.y + a1 * v1.y * v1.y
                      + a2 * v2.y * v2.y + a3 * v3.y * v3.y;
        }
    }
#pragma unroll
    for (int k = 0; k < Kk; k++) {
        size_t idx = (((size_t)b * SPLITS + s) * Kk + k) * (Dd / 2) + t;
        ((__half2*)g_parth)[idx]  = __floats2half2_rn(acc1x[k], acc1y[k]);
        ((__half2*)g_part2h)[idx] = __floats2half2_rn(acc2x[k], acc2y[k]);
    }
}

// reduce: mu = sum parts; sigma = q2 - (2 - S) mu^2; fused next-iter prep ----
__global__ __launch_bounds__(256)
void musig_reduce_kernel() {
    int bk = blockIdx.x;
    int b = bk >> 3, k = bk & 7;
    int t = threadIdx.x;               // 256; owns cols 2t, 2t+1
    float mx = 0.f, my = 0.f, q2x = 0.f, q2y = 0.f;
#pragma unroll 8
    for (int s = 0; s < SPLITS; s++) {
        size_t idx = (((size_t)b * SPLITS + s) * Kk + k) * (Dd / 2) + t;
        float2 p1 = __half22float2(((const __half2*)g_parth)[idx]);
        float2 p2 = __half22float2(((const __half2*)g_part2h)[idx]);
        mx += p1.x; my += p1.y;
        q2x += p2.x; q2y += p2.y;
    }
    float sfac = g_snorm[bk];
    float sigx = q2x - (2.f - sfac) * mx * mx;
    float sigy = q2y - (2.f - sfac) * my * my;
    int i0 = bk * Dd + 2 * t;
    *(float2*)&g_mu[i0]    = make_float2(mx, my);
    *(float2*)&g_sigma[i0] = make_float2(sigx, sigy);
    *(float2*)&g_iv[i0]    = make_float2(1.f / (sigx * sigx + EPSV),
                                         1.f / (sigy * sigy + EPSV));
    float ls = logf(fabsf(sigx) + EPSV) + logf(fabsf(sigy) + EPSV);
#pragma unroll
    for (int o = 16; o > 0; o >>= 1) ls += __shfl_down_sync(0xFFFFFFFFu, ls, o);
    __shared__ float sh[8];
    int w = t >> 5, l = t & 31;
    if (l == 0) sh[w] = ls;
    __syncthreads();
    if (t == 0) {
        float tot = 0.f;
        for (int i = 0; i < 8; i++) tot += sh[i];
        g_c[bk] = -0.5f * (float)Dd * LOG2PI - 0.5f * tot;
    }
}

// ------------------- merged outputs -----------------------------------------
__global__ void out_kernel(const float* __restrict__ noise_final,
                           float* __restrict__ out) {
    int t = threadIdx.x;               // 256
    if (blockIdx.x < Bsz * Kk) {       // slots: 128 blocks, 512 elems each
        int bk = blockIdx.x;
#pragma unroll
        for (int j = 0; j < 2; j++) {
            int i = bk * Dd + t + j * 256;
            float sg = fmaxf(fabsf(g_sigma[i]), EPSV);
            out[i] = g_mu[i] + sg * noise_final[i];
        }
    } else {                           // attn: 512 blocks
        int i = (blockIdx.x - Bsz * Kk) * 256 + t;     // 0..131071
        int n = i & (Nn - 1);
        int k = (i >> 10) & (Kk - 1);
        int b = i >> 13;
        out[Bsz * Kk * Dd + i] = g_attn[((size_t)(b * Nn + n)) * Kk + k]
                                 / (g_colsum[b * Kk + k] + EPSV);
    }
}

// ------------------- launch -------------------------------------------------
extern "C" void kernel_launch(void* const* d_in, const int* in_sizes, int n_in,
                              void* d_out, int out_size) {
    const float* embeddings  = (const float*)d_in[0];
    const float* noise_init  = (const float*)d_in[1];
    const float* noise_final = (const float*)d_in[2];
    const float* slots_mu    = (const float*)d_in[3];
    const float* slots_ls    = (const float*)d_in[4];
    const float* mixc        = (const float*)d_in[5];
    const float* Wk          = (const float*)d_in[6];
    const float* bk          = (const float*)d_in[7];
    const float* Wq          = (const float*)d_in[8];
    const float* bq          = (const float*)d_in[9];
    const float* Wv          = (const float*)d_in[10];
    const float* bv          = (const float*)d_in[11];
    const float* ln_g        = (const float*)d_in[12];
    const float* ln_b        = (const float*)d_in[13];
    float* out = (float*)d_out;

    cudaFuncSetAttribute(gemm_qinit_f16,
                         cudaFuncAttributeMaxDynamicSharedMemorySize, GEMM_SMEM);

    fused_pre_kernel<<<Bsz * Nn + 768, 256>>>(embeddings, Wk, Wv, Wq,     // 1
                                              ln_g, ln_b);
    gemm_qinit_f16<<<dim3(8, 128, 2), 256, GEMM_SMEM>>>(                  // 2
        bk, bv, slots_mu, slots_ls, noise_init, bq, mixc);

    for (int it = 0; it < NITERS; it++) {
        gll_kernel<<<dim3(NCH, Bsz), 256>>>();                            // 3
        musig_part_kernel<<<dim3(SPLITS, Bsz), 256>>>();                  // 4 (profiled, it=0)
        musig_reduce_kernel<<<Bsz * Kk, 256>>>();
    }

    out_kernel<<<Bsz * Kk + (Bsz * Nn * Kk) / 256, 256>>>(noise_final, out);
}